// round 10
// baseline (speedup 1.0000x reference)
#include <cuda_runtime.h>
#include <cuda_bf16.h>

#define N_NODES_MAX 50001
#define DIM 100
#define NEG_SLOPE 0.2f
#define FIX_SCALE 4194304.0f              // 2^22 (folded into hiW)
// exp(s) = exp2( r * log2(e)/2^22 ) where r = redux-int dot
#define EXP2_C 3.440151965051806e-07f     // log2(e) * 2^-22

typedef unsigned long long u64;

// CSR row starts recovered from the sorted seg array. Ring edges guarantee
// every node appears as a segment, so every entry is written each call.
__device__ int g_rowstart[N_NODES_MAX + 1];

__global__ void find_bounds_kernel(const int* __restrict__ seg, int P) {
    int p = blockIdx.x * blockDim.x + threadIdx.x;
    if (p >= P) return;
    int s = seg[p];
    if (p == 0 || seg[p - 1] != s) g_rowstart[s] = p;
    if (p == P - 1) g_rowstart[s + 1] = P;
}

// ---- packed f32x2 helpers (Blackwell; ptxas never auto-fuses these) ----
__device__ __forceinline__ u64 pack2(float lo, float hi) {
    u64 r; asm("mov.b64 %0, {%1, %2};" : "=l"(r) : "f"(lo), "f"(hi)); return r;
}
__device__ __forceinline__ void unpack2(u64 v, float& lo, float& hi) {
    asm("mov.b64 {%0, %1}, %2;" : "=f"(lo), "=f"(hi) : "l"(v));
}
__device__ __forceinline__ u64 mul2(u64 a, u64 b) {
    u64 r; asm("mul.rn.f32x2 %0, %1, %2;" : "=l"(r) : "l"(a), "l"(b)); return r;
}
__device__ __forceinline__ u64 fma2(u64 a, u64 b, u64 c) {
    u64 r; asm("fma.rn.f32x2 %0, %1, %2, %3;" : "=l"(r) : "l"(a), "l"(b), "l"(c));
    return r;
}

// Hardware integer warp reduction (sm_80+): result lands in every lane.
__device__ __forceinline__ int redux_add(int v) {
    int r;
    asm volatile("redux.sync.add.s32 %0, %1, 0xffffffff;" : "=r"(r) : "r"(v));
    return r;
}

__device__ __forceinline__ float ex2(float x) {
    float r;
    asm("ex2.approx.ftz.f32 %0, %1;" : "=f"(r) : "f"(x));
    return r;
}

// scaled score r (int): e = exp(leaky(r * 2^-22)); leaky commutes with
// positive scaling so it is applied to the raw scaled value.
__device__ __forceinline__ float score_exp(int ri) {
    float r = (float)ri;
    float l = fmaxf(r, NEG_SLOPE * r);
    return ex2(l * EXP2_C);
}

// packed dot: sum of both halves of hiW01*v.x + hiW23*v.y
__device__ __forceinline__ float pdot(u64 hiW01, u64 hiW23, ulonglong2 v) {
    u64 t = fma2(hiW23, v.y, mul2(hiW01, v.x));
    float lo, hi; unpack2(t, lo, hi);
    return lo + hi;
}

// One warp per segment. Lane l (l < 25) owns dims [4l, 4l+4); lanes 25-31
// redundantly load lane 24's slice (always in-bounds) — their dot
// contribution is zero (hiW==0 there) and their acc is never stored.
// Max-free softmax: scores are O(+-7), exp cannot overflow; e/z equals the
// max-subtracted reference algebraically.
__global__ void __launch_bounds__(128, 12) agg_fused_kernel(
        const float* __restrict__ hidden,
        const float* __restrict__ W,
        const int*   __restrict__ nbr,
        float*       __restrict__ out,
        int n) {
    int warp = (blockIdx.x * blockDim.x + threadIdx.x) >> 5;
    int lane = threadIdx.x & 31;
    if (warp >= n) return;
    const int v = warp;
    const int cl = min(lane, DIM / 4 - 1);       // clamped lane (25..31 -> 24)
    const float* hp = hidden + cl * 4;           // lane-local base (16B aligned)

    const int s0 = g_rowstart[v];
    const int e0 = g_rowstart[v + 1];

    // hiW = h_i ⊙ W ⊙ 2^22 packed into two f32x2 (zero on lanes >= 25)
    u64 hiW01, hiW23;
    {
        float4 t = make_float4(0.f, 0.f, 0.f, 0.f);
        if (lane < DIM / 4) {
            float4 hi = *reinterpret_cast<const float4*>(hidden + v * DIM + lane * 4);
            float4 w  = *reinterpret_cast<const float4*>(W + lane * 4);
            t.x = hi.x * w.x * FIX_SCALE; t.y = hi.y * w.y * FIX_SCALE;
            t.z = hi.z * w.z * FIX_SCALE; t.w = hi.w * w.w * FIX_SCALE;
        }
        hiW01 = pack2(t.x, t.y);
        hiW23 = pack2(t.z, t.w);
    }

    float z = 0.f;
    u64 acc01 = pack2(0.f, 0.f);
    u64 acc23 = pack2(0.f, 0.f);

    auto scalar_step = [&](int p) {
        int j = nbr[p];
        ulonglong2 H = *reinterpret_cast<const ulonglong2*>(hp + j * DIM);
        float d = pdot(hiW01, hiW23, H);
        float e = score_exp(redux_add(__float2int_rn(d)));
        z += e;
        u64 e2 = pack2(e, e);
        acc01 = fma2(e2, H.x, acc01);
        acc23 = fma2(e2, H.y, acc23);
    };

    int p = s0;
    while (p < e0 && (p & 3)) { scalar_step(p); p++; }   // align for int4

    // 4x main loop: four gathers in flight, shuffle-free, packed f32x2 math
    for (; p + 3 < e0; p += 4) {
        int4 na = *reinterpret_cast<const int4*>(nbr + p);
        ulonglong2 A = *reinterpret_cast<const ulonglong2*>(hp + na.x * DIM);
        ulonglong2 B = *reinterpret_cast<const ulonglong2*>(hp + na.y * DIM);
        ulonglong2 C = *reinterpret_cast<const ulonglong2*>(hp + na.z * DIM);
        ulonglong2 D = *reinterpret_cast<const ulonglong2*>(hp + na.w * DIM);

        float da = pdot(hiW01, hiW23, A);
        float db = pdot(hiW01, hiW23, B);
        float dc = pdot(hiW01, hiW23, C);
        float dd = pdot(hiW01, hiW23, D);

        int ra = redux_add(__float2int_rn(da));
        int rb = redux_add(__float2int_rn(db));
        int rc = redux_add(__float2int_rn(dc));
        int rd = redux_add(__float2int_rn(dd));

        float ea = score_exp(ra);
        float eb = score_exp(rb);
        float ec = score_exp(rc);
        float ed = score_exp(rd);

        u64 ea2 = pack2(ea, ea), eb2 = pack2(eb, eb);
        u64 ec2 = pack2(ec, ec), ed2 = pack2(ed, ed);

        z += (ea + eb) + (ec + ed);
        acc01 = fma2(ea2, A.x, acc01);
        acc23 = fma2(ea2, A.y, acc23);
        acc01 = fma2(eb2, B.x, acc01);
        acc23 = fma2(eb2, B.y, acc23);
        acc01 = fma2(ec2, C.x, acc01);
        acc23 = fma2(ec2, C.y, acc23);
        acc01 = fma2(ed2, D.x, acc01);
        acc23 = fma2(ed2, D.y, acc23);
    }

    for (; p < e0; p++) scalar_step(p);

    float invz = 1.f / z;
    if (lane < DIM / 4) {
        float a0, a1, a2, a3;
        unpack2(acc01, a0, a1);
        unpack2(acc23, a2, a3);
        float4 o4 = make_float4(a0 * invz, a1 * invz, a2 * invz, a3 * invz);
        *reinterpret_cast<float4*>(out + v * DIM + lane * 4) = o4;
    }
}

extern "C" void kernel_launch(void* const* d_in, const int* in_sizes, int n_in,
                              void* d_out, int out_size) {
    const float* hidden = (const float*)d_in[0];
    const float* W      = (const float*)d_in[1];
    const int*   seg    = (const int*)d_in[2];
    const int*   nbr    = (const int*)d_in[3];
    float*       out    = (float*)d_out;

    const int D = in_sizes[1];          // 100
    const int n = in_sizes[0] / D;      // 50000
    const int P = in_sizes[2];

    find_bounds_kernel<<<(P + 255) / 256, 256>>>(seg, P);

    const int threads = 128;            // 4 warps/block, 12 blocks/SM target
    const int blocks = (n * 32 + threads - 1) / threads;
    agg_fused_kernel<<<blocks, threads>>>(hidden, W, nbr, out, n);
}